// round 2
// baseline (speedup 1.0000x reference)
#include <cuda_runtime.h>

#define N_NODES 8
#define B_      4
#define C_      32
#define HW      9216          // 96*96
#define TILE    64            // pixels per block
#define PADROW  68            // padded row stride (floats): 272B, 16B-aligned rows
#define NGROUP  (TILE / 4)    // 4-pixel groups per tile
#define NTILES  (HW / TILE)   // 144
#define TOTAL   (N_NODES * B_ * C_ * HW)  // 9437184
#define SMEM_BYTES (N_NODES * C_ * PADROW * 4)  // 69632

// Ping-pong scratch (no runtime allocation allowed).
__device__ float g_buf0[TOTAL];
__device__ float g_buf1[TOTAL];

// ---- packed f32x2 helpers (sm_100+ PTX; emits FFMA2 SASS) ----
__device__ __forceinline__ unsigned long long fma_f32x2(
    unsigned long long a, unsigned long long b, unsigned long long c) {
    unsigned long long d;
    asm("fma.rn.f32x2 %0, %1, %2, %3;" : "=l"(d) : "l"(a), "l"(b), "l"(c));
    return d;
}
__device__ __forceinline__ unsigned long long add_f32x2(
    unsigned long long a, unsigned long long b) {
    unsigned long long d;
    asm("add.rn.f32x2 %0, %1, %2;" : "=l"(d) : "l"(a), "l"(b));
    return d;
}
union U2 { unsigned long long u; float2 f; };
__device__ __forceinline__ unsigned long long pack2(float lo, float hi) {
    U2 t; t.f.x = lo; t.f.y = hi; return t.u;
}

// One message-passing step:
// out[i] = x_i + sum_{j!=i} relu(Wd_i @ x_j + c_i) * x_j
// where c_i = (Ws_i - Wd_i) @ x_i + b_i
extern "C" __global__ void __launch_bounds__(256)
step_kernel(const float* __restrict__ in,
            const float* __restrict__ W_edge,   // [8,32,64]: [:, :, :32]=Wd, [:, :, 32:]=Ws
            const float* __restrict__ b_edge,   // [8,32]
            float* __restrict__ out)
{
    extern __shared__ float xs[];   // [8*32][PADROW] : xs[node*32+c][p]

    const int b       = blockIdx.x / NTILES;
    const int tileIdx = blockIdx.x % NTILES;
    const int p_base  = tileIdx * TILE;
    const int tid     = threadIdx.x;
    const int i       = tid >> 5;   // receiver = warp
    const int o       = tid & 31;   // output channel = lane

    // ---- cooperative tile load: 256 rows x 64 floats (coalesced float4) ----
    #pragma unroll
    for (int k = 0; k < 16; ++k) {
        const int e    = tid + k * 256;       // 0..4095
        const int row  = e >> 4;              // node*32 + c
        const int col4 = e & 15;
        const int node = row >> 5;
        const int c    = row & 31;
        const float4 v = *reinterpret_cast<const float4*>(
            in + ((node * B_ + b) * C_ + c) * HW + p_base + col4 * 4);
        *reinterpret_cast<float4*>(xs + row * PADROW + col4 * 4) = v;
    }

    // ---- weights into registers (per-thread: receiver i, out-channel o) ----
    unsigned long long Wd2[C_];   // packed {wd, wd}
    float Wc[C_];                 // ws - wd
    {
        const float* wrow = W_edge + (i * C_ + o) * (2 * C_);
        #pragma unroll
        for (int d = 0; d < C_; ++d) {
            const float wd = wrow[d];
            const float ws = wrow[C_ + d];
            Wd2[d] = pack2(wd, wd);
            Wc[d]  = ws - wd;
        }
    }
    const float bias = b_edge[i * C_ + o];

    __syncthreads();

    const float* rowI = xs + (i * C_) * PADROW;

    for (int q = 0; q < NGROUP; ++q) {
        const int p0 = q * 4;

        // ---- c_i for 4 pixels (scalar FFMA, 1/8 of the work) ----
        float c0 = bias, c1 = bias, c2 = bias, c3 = bias;
        #pragma unroll
        for (int d = 0; d < C_; ++d) {
            const float4 xv = *reinterpret_cast<const float4*>(rowI + d * PADROW + p0);
            c0 = fmaf(Wc[d], xv.x, c0);
            c1 = fmaf(Wc[d], xv.y, c1);
            c2 = fmaf(Wc[d], xv.z, c2);
            c3 = fmaf(Wc[d], xv.w, c3);
        }
        const unsigned long long ciA = pack2(c0, c1);
        const unsigned long long ciB = pack2(c2, c3);

        // residual init: acc = x_i[o][p0..p3]
        float4 acc = *reinterpret_cast<const float4*>(rowI + o * PADROW + p0);

        #pragma unroll
        for (int j = 0; j < N_NODES; ++j) {
            if (j == i) continue;            // warp-uniform branch
            const float* rowJ = xs + (j * C_) * PADROW;

            // y = Wd_i @ x_j + c_i ; 4 independent FFMA2 chains for ILP
            unsigned long long yA0 = ciA, yA1 = 0ull;   // pixels p0,p1
            unsigned long long yB0 = ciB, yB1 = 0ull;   // pixels p2,p3
            #pragma unroll
            for (int d = 0; d < C_; d += 2) {
                const ulonglong2 xv0 = *reinterpret_cast<const ulonglong2*>(rowJ + d * PADROW + p0);
                yA0 = fma_f32x2(Wd2[d], xv0.x, yA0);
                yB0 = fma_f32x2(Wd2[d], xv0.y, yB0);
                const ulonglong2 xv1 = *reinterpret_cast<const ulonglong2*>(rowJ + (d + 1) * PADROW + p0);
                yA1 = fma_f32x2(Wd2[d + 1], xv1.x, yA1);
                yB1 = fma_f32x2(Wd2[d + 1], xv1.y, yB1);
            }
            U2 yA; yA.u = add_f32x2(yA0, yA1);
            U2 yB; yB.u = add_f32x2(yB0, yB1);

            // gate * x_j[o]
            const float4 xg = *reinterpret_cast<const float4*>(rowJ + o * PADROW + p0);
            acc.x = fmaf(fmaxf(yA.f.x, 0.0f), xg.x, acc.x);
            acc.y = fmaf(fmaxf(yA.f.y, 0.0f), xg.y, acc.y);
            acc.z = fmaf(fmaxf(yB.f.x, 0.0f), xg.z, acc.z);
            acc.w = fmaf(fmaxf(yB.f.y, 0.0f), xg.w, acc.w);
        }

        *reinterpret_cast<float4*>(
            out + ((i * B_ + b) * C_ + o) * HW + p_base + p0) = acc;
    }
}

extern "C" void kernel_launch(void* const* d_in, const int* in_sizes, int n_in,
                              void* d_out, int out_size) {
    const float* nodes = (const float*)d_in[0];
    const float* W     = (const float*)d_in[1];
    const float* bvec  = (const float*)d_in[2];
    float* out         = (float*)d_out;

    float *buf0 = nullptr, *buf1 = nullptr;
    cudaGetSymbolAddress((void**)&buf0, g_buf0);
    cudaGetSymbolAddress((void**)&buf1, g_buf1);

    cudaFuncSetAttribute(step_kernel,
                         cudaFuncAttributeMaxDynamicSharedMemorySize, SMEM_BYTES);

    const dim3 grid(B_ * NTILES);   // 576 blocks
    const dim3 block(256);

    // 3 steps: in -> buf0 -> buf1 -> out
    step_kernel<<<grid, block, SMEM_BYTES>>>(nodes, W, bvec, buf0);
    step_kernel<<<grid, block, SMEM_BYTES>>>(buf0,  W, bvec, buf1);
    step_kernel<<<grid, block, SMEM_BYTES>>>(buf1,  W, bvec, out);
}